// round 2
// baseline (speedup 1.0000x reference)
#include <cuda_runtime.h>
#include <math.h>
#include <stdint.h>

#define B_  2
#define S_  2048
#define D_  1024
#define H_  16
#define HD_ 64
#define M_TOT (B_*S_)   // 4096

// Scratch (device globals — no runtime allocation allowed)
__device__ float g_q[B_*H_*S_*HD_];
__device__ float g_k[B_*H_*S_*HD_];
__device__ float g_v[B_*H_*S_*HD_];
__device__ float g_attn[B_*S_*D_];

// ---------------------------------------------------------------------------
// TF32 tensor-core GEMM: C = A @ W^T + bias
// A:[M,K] row-major, W:[N,K] row-major, K = 1024.
// Block tile 128x128, BK=16, 256 threads = 8 warps, warp tile 64x32.
// mma.sync.m16n8k8.tf32 (fallback HMMA on sm_103a).
//
// Smem layout: row = output-dim index (m for A, n for W), 16 words per row
// holding the k-slab in permuted order k' = (k&3)*4 + (k>>2), with the
// 4-word chunk index XOR-swizzled by ((row>>1)&3). This makes:
//   - STS.32 staging stores conflict-free
//   - fragment loads ONE LDS.128 per tile-row, conflict-free
// ---------------------------------------------------------------------------
__device__ __forceinline__ uint32_t f2tf(float x) {
    uint32_t r;
    asm("cvt.rna.tf32.f32 %0, %1;" : "=r"(r) : "f"(x));
    return r;
}

__device__ __forceinline__ void mma8(float* c,
                                     uint32_t a0, uint32_t a1, uint32_t a2, uint32_t a3,
                                     uint32_t b0, uint32_t b1)
{
    asm volatile(
        "mma.sync.aligned.m16n8k8.row.col.f32.tf32.tf32.f32 "
        "{%0,%1,%2,%3}, {%4,%5,%6,%7}, {%8,%9}, {%0,%1,%2,%3};\n"
        : "+f"(c[0]), "+f"(c[1]), "+f"(c[2]), "+f"(c[3])
        : "r"(a0), "r"(a1), "r"(a2), "r"(a3), "r"(b0), "r"(b1));
}

template<int SPLIT>
__global__ __launch_bounds__(256, 2)
void gemm_tf32(const float* __restrict__ A, const float* __restrict__ W,
               const float* __restrict__ bias, float* __restrict__ C)
{
    const int K = D_;
    __shared__ uint32_t As[128 * 16];
    __shared__ uint32_t Ws[128 * 16];

    const int tid  = threadIdx.x;
    const int m0   = blockIdx.y * 128;
    const int n0   = blockIdx.x * 128;
    const int lane = tid & 31;
    const int wid  = tid >> 5;
    const int wm   = (wid & 1) * 64;   // warp m-offset within block
    const int wn   = (wid >> 1) * 32;  // warp n-offset within block
    const int g    = lane >> 2;        // 0..7
    const int tig  = lane & 3;         // 0..3

    // staging indices
    const int ar = tid >> 2;          // 0..63 (rows ar, ar+64)
    const int ac = tid & 3;           // k-group: k = ac*4 + i

    float Cr[4][4][4];
    #pragma unroll
    for (int mt = 0; mt < 4; mt++)
        #pragma unroll
        for (int nt = 0; nt < 4; nt++)
            #pragma unroll
            for (int i = 0; i < 4; i++) Cr[mt][nt][i] = 0.f;

    for (int k0 = 0; k0 < K; k0 += 16) {
        // ---- stage A and W slabs into swizzled smem ----
        #pragma unroll
        for (int rr = 0; rr < 2; rr++) {
            int row = ar + rr * 64;
            int sw  = (row >> 1) & 3;
            int base = row * 16;
            float4 av = *(const float4*)&A[(size_t)(m0 + row) * K + k0 + ac * 4];
            As[base + (((0 ^ sw) << 2) + ac)] = f2tf(av.x);
            As[base + (((1 ^ sw) << 2) + ac)] = f2tf(av.y);
            As[base + (((2 ^ sw) << 2) + ac)] = f2tf(av.z);
            As[base + (((3 ^ sw) << 2) + ac)] = f2tf(av.w);
            float4 wv = *(const float4*)&W[(size_t)(n0 + row) * K + k0 + ac * 4];
            Ws[base + (((0 ^ sw) << 2) + ac)] = f2tf(wv.x);
            Ws[base + (((1 ^ sw) << 2) + ac)] = f2tf(wv.y);
            Ws[base + (((2 ^ sw) << 2) + ac)] = f2tf(wv.z);
            Ws[base + (((3 ^ sw) << 2) + ac)] = f2tf(wv.w);
        }
        __syncthreads();

        // ---- fragment loads: one LDS.128 per tile-row ----
        uint4 Aq[4][2];
        #pragma unroll
        for (int mt = 0; mt < 4; mt++) {
            int r0 = wm + mt * 16 + g;
            Aq[mt][0] = *(const uint4*)&As[r0 * 16 + ((tig ^ ((r0 >> 1) & 3)) << 2)];
            int r1 = r0 + 8;
            Aq[mt][1] = *(const uint4*)&As[r1 * 16 + ((tig ^ ((r1 >> 1) & 3)) << 2)];
        }
        uint4 Bq[4];
        #pragma unroll
        for (int nt = 0; nt < 4; nt++) {
            int rn = wn + nt * 8 + g;
            Bq[nt] = *(const uint4*)&Ws[rn * 16 + ((tig ^ ((rn >> 1) & 3)) << 2)];
        }

        // ---- 2 k-steps x 16 mma ----
        #pragma unroll
        for (int mt = 0; mt < 4; mt++)
            #pragma unroll
            for (int nt = 0; nt < 4; nt++)
                mma8(Cr[mt][nt], Aq[mt][0].x, Aq[mt][1].x, Aq[mt][0].y, Aq[mt][1].y,
                     Bq[nt].x, Bq[nt].y);
        #pragma unroll
        for (int mt = 0; mt < 4; mt++)
            #pragma unroll
            for (int nt = 0; nt < 4; nt++)
                mma8(Cr[mt][nt], Aq[mt][0].z, Aq[mt][1].z, Aq[mt][0].w, Aq[mt][1].w,
                     Bq[nt].z, Bq[nt].w);

        __syncthreads();
    }

    // ---- epilogue: add bias, write (optionally scattered to [B,H,S,HD]) ----
    #pragma unroll
    for (int mt = 0; mt < 4; mt++) {
        #pragma unroll
        for (int nt = 0; nt < 4; nt++) {
            int m = m0 + wm + mt * 16 + g;
            int n = n0 + wn + nt * 8 + tig * 2;
            float b0v = bias[n], b1v = bias[n + 1];
            float2 v0 = make_float2(Cr[mt][nt][0] + b0v, Cr[mt][nt][1] + b1v);
            float2 v1 = make_float2(Cr[mt][nt][2] + b0v, Cr[mt][nt][3] + b1v);
            if (SPLIT) {
                int b  = m >> 11;          // m / S_
                int s  = m & (S_ - 1);
                int h  = n >> 6;
                int hd = n & 63;
                float* p0 = &C[(size_t)(((b * H_ + h) * S_) + s) * HD_ + hd];
                *(float2*)p0 = v0;
                int s2 = (m + 8) & (S_ - 1);
                int b2 = (m + 8) >> 11;
                float* p1 = &C[(size_t)(((b2 * H_ + h) * S_) + s2) * HD_ + hd];
                *(float2*)p1 = v1;
            } else {
                *(float2*)&C[(size_t)m * D_ + n] = v0;
                *(float2*)&C[(size_t)(m + 8) * D_ + n] = v1;
            }
        }
    }
}

// ---------------------------------------------------------------------------
// Flash-style attention over [B,H,S,HD] Q/K/V, writes [B,S,D] output.
// (unchanged from round 1)
// ---------------------------------------------------------------------------
#define QSTRIDE 68
#define PSTRIDE 65

__global__ __launch_bounds__(256)
void attn_kernel(const int* __restrict__ mask)
{
    extern __shared__ float sm[];
    float* Qs = sm;
    float* Ks = Qs + 64*QSTRIDE;
    float* Ps = Ks + 64*QSTRIDE;
    int*  Msk = (int*)(Ps + 64*PSTRIDE);

    const int tid = threadIdx.x;
    const int bh  = blockIdx.y;
    const int b   = bh >> 4;
    const int h   = bh & 15;
    const int q0  = blockIdx.x * 64;
    const int qg  = tid >> 3;
    const int c   = tid & 7;

    const float* qbase = g_q + ((size_t)bh * S_ + q0) * HD_;
    const float* kbase = g_k + (size_t)bh * S_ * HD_;
    const float* vbase = g_v + (size_t)bh * S_ * HD_;

    for (int i = tid; i < 64*16; i += 256) {
        int r = i >> 4, c4 = (i & 15) << 2;
        *(float4*)&Qs[r*QSTRIDE + c4] = *(const float4*)&qbase[r*64 + c4];
    }
    for (int i = tid; i < S_; i += 256) Msk[i] = mask[b*S_ + i];

    float mrow[2] = {-1e30f, -1e30f};
    float lrow[2] = {0.f, 0.f};
    float acc[2][8];
    #pragma unroll
    for (int qi = 0; qi < 2; qi++)
        #pragma unroll
        for (int dd = 0; dd < 8; dd++) acc[qi][dd] = 0.f;

    __syncthreads();

    for (int kt = 0; kt < S_/64; kt++) {
        const float* ksrc = kbase + kt * 64 * 64;
        for (int i = tid; i < 64*16; i += 256) {
            int r = i >> 4, c4 = (i & 15) << 2;
            *(float4*)&Ks[r*QSTRIDE + c4] = *(const float4*)&ksrc[r*64 + c4];
        }
        __syncthreads();

        float s[2][8];
        #pragma unroll
        for (int qi = 0; qi < 2; qi++)
            #pragma unroll
            for (int jj = 0; jj < 8; jj++) s[qi][jj] = 0.f;

        for (int d4 = 0; d4 < 64; d4 += 4) {
            float4 qa = *(const float4*)&Qs[qg*QSTRIDE + d4];
            float4 qb = *(const float4*)&Qs[(qg+32)*QSTRIDE + d4];
            #pragma unroll
            for (int jj = 0; jj < 8; jj++) {
                float4 kv = *(const float4*)&Ks[(jj*8 + c)*QSTRIDE + d4];
                s[0][jj] += qa.x*kv.x + qa.y*kv.y + qa.z*kv.z + qa.w*kv.w;
                s[1][jj] += qb.x*kv.x + qb.y*kv.y + qb.z*kv.z + qb.w*kv.w;
            }
        }

        const int jb = kt * 64;
        #pragma unroll
        for (int jj = 0; jj < 8; jj++) {
            int j = jj*8 + c;
            bool ok = (Msk[jb + j] != 0);
            s[0][jj] = ok ? s[0][jj] * 0.125f : -1.0e9f;
            s[1][jj] = ok ? s[1][jj] * 0.125f : -1.0e9f;
        }

        float t0 = -1e30f, t1 = -1e30f;
        #pragma unroll
        for (int jj = 0; jj < 8; jj++) {
            t0 = fmaxf(t0, s[0][jj]);
            t1 = fmaxf(t1, s[1][jj]);
        }
        #pragma unroll
        for (int o = 1; o < 8; o <<= 1) {
            t0 = fmaxf(t0, __shfl_xor_sync(0xffffffffu, t0, o));
            t1 = fmaxf(t1, __shfl_xor_sync(0xffffffffu, t1, o));
        }
        float mn0 = fmaxf(mrow[0], t0), mn1 = fmaxf(mrow[1], t1);
        float cor0 = __expf(mrow[0] - mn0), cor1 = __expf(mrow[1] - mn1);
        float ps0 = 0.f, ps1 = 0.f;
        #pragma unroll
        for (int jj = 0; jj < 8; jj++) {
            int j = jj*8 + c;
            float p0 = __expf(s[0][jj] - mn0);
            float p1 = __expf(s[1][jj] - mn1);
            Ps[qg*PSTRIDE + j]       = p0;
            Ps[(qg+32)*PSTRIDE + j]  = p1;
            ps0 += p0; ps1 += p1;
        }
        #pragma unroll
        for (int o = 1; o < 8; o <<= 1) {
            ps0 += __shfl_xor_sync(0xffffffffu, ps0, o);
            ps1 += __shfl_xor_sync(0xffffffffu, ps1, o);
        }
        lrow[0] = lrow[0]*cor0 + ps0;
        lrow[1] = lrow[1]*cor1 + ps1;
        mrow[0] = mn0; mrow[1] = mn1;
        #pragma unroll
        for (int dd = 0; dd < 8; dd++) { acc[0][dd] *= cor0; acc[1][dd] *= cor1; }

        __syncthreads();

        const float* vsrc = vbase + kt * 64 * 64;
        for (int i = tid; i < 64*16; i += 256) {
            int r = i >> 4, c4 = (i & 15) << 2;
            *(float4*)&Ks[r*QSTRIDE + c4] = *(const float4*)&vsrc[r*64 + c4];
        }
        __syncthreads();

        for (int j = 0; j < 64; j++) {
            float p0 = Ps[qg*PSTRIDE + j];
            float p1 = Ps[(qg+32)*PSTRIDE + j];
            float4 va = *(const float4*)&Ks[j*QSTRIDE + c*8];
            float4 vb = *(const float4*)&Ks[j*QSTRIDE + c*8 + 4];
            acc[0][0] += p0*va.x; acc[0][1] += p0*va.y;
            acc[0][2] += p0*va.z; acc[0][3] += p0*va.w;
            acc[0][4] += p0*vb.x; acc[0][5] += p0*vb.y;
            acc[0][6] += p0*vb.z; acc[0][7] += p0*vb.w;
            acc[1][0] += p1*va.x; acc[1][1] += p1*va.y;
            acc[1][2] += p1*va.z; acc[1][3] += p1*va.w;
            acc[1][4] += p1*vb.x; acc[1][5] += p1*vb.y;
            acc[1][6] += p1*vb.z; acc[1][7] += p1*vb.w;
        }
        __syncthreads();
    }

    float inv0 = 1.0f / lrow[0];
    float inv1 = 1.0f / lrow[1];
    float* outp = g_attn + ((size_t)(b*S_ + q0)) * D_ + h * HD_;
    float4 o;
    o.x = acc[0][0]*inv0; o.y = acc[0][1]*inv0; o.z = acc[0][2]*inv0; o.w = acc[0][3]*inv0;
    *(float4*)&outp[(size_t)qg * D_ + c*8]     = o;
    o.x = acc[0][4]*inv0; o.y = acc[0][5]*inv0; o.z = acc[0][6]*inv0; o.w = acc[0][7]*inv0;
    *(float4*)&outp[(size_t)qg * D_ + c*8 + 4] = o;
    o.x = acc[1][0]*inv1; o.y = acc[1][1]*inv1; o.z = acc[1][2]*inv1; o.w = acc[1][3]*inv1;
    *(float4*)&outp[(size_t)(qg+32) * D_ + c*8]     = o;
    o.x = acc[1][4]*inv1; o.y = acc[1][5]*inv1; o.z = acc[1][6]*inv1; o.w = acc[1][7]*inv1;
    *(float4*)&outp[(size_t)(qg+32) * D_ + c*8 + 4] = o;
}

// ---------------------------------------------------------------------------
extern "C" void kernel_launch(void* const* d_in, const int* in_sizes, int n_in,
                              void* d_out, int out_size)
{
    const float* xq  = (const float*)d_in[0];
    const float* xk  = (const float*)d_in[1];
    const float* xv  = (const float*)d_in[2];
    const int*   msk = (const int*)  d_in[3];
    const float* wq  = (const float*)d_in[4];
    const float* bq  = (const float*)d_in[5];
    const float* wk  = (const float*)d_in[6];
    const float* bk  = (const float*)d_in[7];
    const float* wv  = (const float*)d_in[8];
    const float* bv  = (const float*)d_in[9];
    const float* wo  = (const float*)d_in[10];
    const float* bo  = (const float*)d_in[11];

    float *qp, *kp, *vp, *ap;
    cudaGetSymbolAddress((void**)&qp, g_q);
    cudaGetSymbolAddress((void**)&kp, g_k);
    cudaGetSymbolAddress((void**)&vp, g_v);
    cudaGetSymbolAddress((void**)&ap, g_attn);

    const int attn_smem = (64*QSTRIDE*2 + 64*PSTRIDE) * (int)sizeof(float)
                        + S_ * (int)sizeof(int);
    static bool attr_set = false;
    if (!attr_set) {
        cudaFuncSetAttribute(attn_kernel,
                             cudaFuncAttributeMaxDynamicSharedMemorySize, attn_smem);
        attr_set = true;
    }

    dim3 gg(D_/128, M_TOT/128);  // (8, 32)
    gemm_tf32<1><<<gg, 256>>>(xq, wq, bq, qp);
    gemm_tf32<1><<<gg, 256>>>(xk, wk, bk, kp);
    gemm_tf32<1><<<gg, 256>>>(xv, wv, bv, vp);

    dim3 ga(S_/64, B_*H_);       // (32, 32)
    attn_kernel<<<ga, 256, attn_smem>>>(msk);

    gemm_tf32<0><<<gg, 256>>>(ap, wo, bo, (float*)d_out);
}

// round 4
// speedup vs baseline: 1.5708x; 1.5708x over previous
#include <cuda_runtime.h>
#include <math.h>

#define B_  2
#define S_  2048
#define D_  1024
#define H_  16
#define HD_ 64
#define M_TOT (B_*S_)   // 4096

// Scratch (device globals — no runtime allocation allowed)
__device__ float g_q[B_*H_*S_*HD_];
__device__ float g_k[B_*H_*S_*HD_];
__device__ float g_v[B_*H_*S_*HD_];
__device__ float g_attn[B_*S_*D_];

// ---------------------------------------------------------------------------
// GEMM: C = A @ W^T + bias.   A:[M,K] row-major, W:[N,K] row-major.
// 128x128 tile, BK=16, 256 threads, 8x8 per-thread register tile. (round-1,
// measured ~fp32-FMA-roofline; tf32 mma.sync path measured SLOWER on sm_103a)
// SPLIT=1: scatter output to [B,H,S,HD] layout (for Q/K/V).
// ---------------------------------------------------------------------------
template<int SPLIT>
__global__ __launch_bounds__(256)
void gemm_bias(const float* __restrict__ A, const float* __restrict__ W,
               const float* __restrict__ bias, float* __restrict__ C)
{
    const int K = D_;
    __shared__ float As[16][128];
    __shared__ float Ws[16][128];

    const int tid = threadIdx.x;
    const int m0 = blockIdx.y * 128;
    const int n0 = blockIdx.x * 128;
    const int ar = tid >> 2;          // 0..63
    const int ac = (tid & 3) * 4;     // 0,4,8,12
    const int ty = tid >> 4;          // 0..15
    const int tx = tid & 15;          // 0..15

    float acc[8][8];
    #pragma unroll
    for (int i = 0; i < 8; i++)
        #pragma unroll
        for (int j = 0; j < 8; j++) acc[i][j] = 0.f;

    for (int k0 = 0; k0 < K; k0 += 16) {
        #pragma unroll
        for (int rr = 0; rr < 2; rr++) {
            int row = ar + rr * 64;
            float4 av = *(const float4*)&A[(size_t)(m0 + row) * K + k0 + ac];
            As[ac+0][row] = av.x; As[ac+1][row] = av.y;
            As[ac+2][row] = av.z; As[ac+3][row] = av.w;
            float4 wv = *(const float4*)&W[(size_t)(n0 + row) * K + k0 + ac];
            Ws[ac+0][row] = wv.x; Ws[ac+1][row] = wv.y;
            Ws[ac+2][row] = wv.z; Ws[ac+3][row] = wv.w;
        }
        __syncthreads();
        #pragma unroll
        for (int kk = 0; kk < 16; kk++) {
            float a[8], b[8];
            *(float4*)&a[0] = *(const float4*)&As[kk][ty*8];
            *(float4*)&a[4] = *(const float4*)&As[kk][ty*8+4];
            *(float4*)&b[0] = *(const float4*)&Ws[kk][tx*8];
            *(float4*)&b[4] = *(const float4*)&Ws[kk][tx*8+4];
            #pragma unroll
            for (int i = 0; i < 8; i++)
                #pragma unroll
                for (int j = 0; j < 8; j++)
                    acc[i][j] += a[i] * b[j];
        }
        __syncthreads();
    }

    #pragma unroll
    for (int i = 0; i < 8; i++) {
        int m = m0 + ty*8 + i;
        #pragma unroll
        for (int j4 = 0; j4 < 2; j4++) {
            int n = n0 + tx*8 + j4*4;
            float4 v;
            v.x = acc[i][j4*4+0] + bias[n+0];
            v.y = acc[i][j4*4+1] + bias[n+1];
            v.z = acc[i][j4*4+2] + bias[n+2];
            v.w = acc[i][j4*4+3] + bias[n+3];
            if (SPLIT) {
                int b  = m >> 11;          // m / S_
                int s  = m & (S_ - 1);
                int h  = n >> 6;           // n / HD_
                int hd = n & 63;
                *(float4*)&C[(size_t)(((b*H_ + h)*S_) + s) * HD_ + hd] = v;
            } else {
                *(float4*)&C[(size_t)m * D_ + n] = v;
            }
        }
    }
}

// ---------------------------------------------------------------------------
// Flash-style attention, [B,H,S,HD] Q/K/V -> [B,S,D] output.
// Block tile: 128 queries x 64 keys for one (b,h). 256 threads.
// Thread = (qg 0..31, c 0..7): owns q rows {qg+32*qi}, score cols j=jj*8+c,
// output dims c*8..c*8+7. 4 q-rows/thread => 1.5 smem-bytes per FMA
// (FMA-bound; round-1's 2 q-rows was 2.5 B/FMA => L1-bound at 90%).
// Separate K and V buffers; mask read via broadcast LDG (L1-cached).
// ---------------------------------------------------------------------------
#define QSTRIDE 68   // 64 + 4 pad, float4-aligned
#define PSTRIDE 65

__global__ __launch_bounds__(256, 2)
void attn_kernel(const int* __restrict__ mask)
{
    extern __shared__ float sm[];
    float* Qs = sm;                        // 128*68
    float* Ks = Qs + 128*QSTRIDE;          // 64*68
    float* Vs = Ks + 64*QSTRIDE;           // 64*68
    float* Ps = Vs + 64*QSTRIDE;           // 128*65

    const int tid = threadIdx.x;
    const int bh  = blockIdx.y;            // 0..B*H-1
    const int b   = bh >> 4;               // / H_
    const int h   = bh & 15;
    const int q0  = blockIdx.x * 128;
    const int qg  = tid >> 3;              // 0..31
    const int c   = tid & 7;               // 0..7

    const float* qbase = g_q + ((size_t)bh * S_ + q0) * HD_;
    const float* kbase = g_k + (size_t)bh * S_ * HD_;
    const float* vbase = g_v + (size_t)bh * S_ * HD_;
    const int*   mbase = mask + b * S_;

    // Load Q tile (128 rows x 16 float4, coalesced)
    for (int i = tid; i < 128*16; i += 256) {
        int r = i >> 4, c4 = (i & 15) << 2;
        *(float4*)&Qs[r*QSTRIDE + c4] = *(const float4*)&qbase[r*64 + c4];
    }

    float mrow[4] = {-1e30f, -1e30f, -1e30f, -1e30f};
    float lrow[4] = {0.f, 0.f, 0.f, 0.f};
    float acc[4][8];
    #pragma unroll
    for (int qi = 0; qi < 4; qi++)
        #pragma unroll
        for (int dd = 0; dd < 8; dd++) acc[qi][dd] = 0.f;

    __syncthreads();

    for (int kt = 0; kt < S_/64; kt++) {
        // --- load K and V tiles (64 rows x 16 float4 each) ---
        const float* ksrc = kbase + kt * 64 * 64;
        const float* vsrc = vbase + kt * 64 * 64;
        for (int i = tid; i < 64*16; i += 256) {
            int r = i >> 4, c4 = (i & 15) << 2;
            *(float4*)&Ks[r*QSTRIDE + c4] = *(const float4*)&ksrc[r*64 + c4];
            *(float4*)&Vs[r*QSTRIDE + c4] = *(const float4*)&vsrc[r*64 + c4];
        }
        __syncthreads();

        // --- scores: s[qi][jj] = Q[qg+32*qi] . K[jj*8+c] ---
        float s[4][8];
        #pragma unroll
        for (int qi = 0; qi < 4; qi++)
            #pragma unroll
            for (int jj = 0; jj < 8; jj++) s[qi][jj] = 0.f;

        #pragma unroll 4
        for (int d4 = 0; d4 < 64; d4 += 4) {
            float4 qv[4];
            #pragma unroll
            for (int qi = 0; qi < 4; qi++)
                qv[qi] = *(const float4*)&Qs[(qg + 32*qi)*QSTRIDE + d4];
            #pragma unroll
            for (int jj = 0; jj < 8; jj++) {
                float4 kv = *(const float4*)&Ks[(jj*8 + c)*QSTRIDE + d4];
                #pragma unroll
                for (int qi = 0; qi < 4; qi++) {
                    s[qi][jj] = fmaf(qv[qi].x, kv.x, s[qi][jj]);
                    s[qi][jj] = fmaf(qv[qi].y, kv.y, s[qi][jj]);
                    s[qi][jj] = fmaf(qv[qi].z, kv.z, s[qi][jj]);
                    s[qi][jj] = fmaf(qv[qi].w, kv.w, s[qi][jj]);
                }
            }
        }

        // --- mask + scale (mask via broadcast LDG, L1-hit) ---
        const int jb = kt * 64;
        #pragma unroll
        for (int jj = 0; jj < 8; jj++) {
            bool ok = (__ldg(&mbase[jb + jj*8 + c]) != 0);
            #pragma unroll
            for (int qi = 0; qi < 4; qi++)
                s[qi][jj] = ok ? s[qi][jj] * 0.125f : -1.0e9f;
        }

        // --- online softmax update (reduce over 8-lane c-group) ---
        float t[4];
        #pragma unroll
        for (int qi = 0; qi < 4; qi++) {
            t[qi] = s[qi][0];
            #pragma unroll
            for (int jj = 1; jj < 8; jj++) t[qi] = fmaxf(t[qi], s[qi][jj]);
        }
        #pragma unroll
        for (int o = 1; o < 8; o <<= 1)
            #pragma unroll
            for (int qi = 0; qi < 4; qi++)
                t[qi] = fmaxf(t[qi], __shfl_xor_sync(0xffffffffu, t[qi], o));

        float cor[4], ps[4];
        #pragma unroll
        for (int qi = 0; qi < 4; qi++) {
            float mn = fmaxf(mrow[qi], t[qi]);
            cor[qi] = __expf(mrow[qi] - mn);
            mrow[qi] = mn;
            ps[qi] = 0.f;
            #pragma unroll
            for (int jj = 0; jj < 8; jj++) {
                float p = __expf(s[qi][jj] - mn);
                Ps[(qg + 32*qi)*PSTRIDE + jj*8 + c] = p;
                ps[qi] += p;
            }
        }
        #pragma unroll
        for (int o = 1; o < 8; o <<= 1)
            #pragma unroll
            for (int qi = 0; qi < 4; qi++)
                ps[qi] += __shfl_xor_sync(0xffffffffu, ps[qi], o);
        #pragma unroll
        for (int qi = 0; qi < 4; qi++) {
            lrow[qi] = lrow[qi]*cor[qi] + ps[qi];
            #pragma unroll
            for (int dd = 0; dd < 8; dd++) acc[qi][dd] *= cor[qi];
        }

        __syncthreads();   // Ps writes visible; K reads done

        // --- PV: acc[qi][dd] += sum_j P[q][j] * V[j][c*8+dd] ---
        #pragma unroll 2
        for (int j = 0; j < 64; j++) {
            float p[4];
            #pragma unroll
            for (int qi = 0; qi < 4; qi++)
                p[qi] = Ps[(qg + 32*qi)*PSTRIDE + j];
            float4 va = *(const float4*)&Vs[j*QSTRIDE + c*8];
            float4 vb = *(const float4*)&Vs[j*QSTRIDE + c*8 + 4];
            #pragma unroll
            for (int qi = 0; qi < 4; qi++) {
                acc[qi][0] = fmaf(p[qi], va.x, acc[qi][0]);
                acc[qi][1] = fmaf(p[qi], va.y, acc[qi][1]);
                acc[qi][2] = fmaf(p[qi], va.z, acc[qi][2]);
                acc[qi][3] = fmaf(p[qi], va.w, acc[qi][3]);
                acc[qi][4] = fmaf(p[qi], vb.x, acc[qi][4]);
                acc[qi][5] = fmaf(p[qi], vb.y, acc[qi][5]);
                acc[qi][6] = fmaf(p[qi], vb.z, acc[qi][6]);
                acc[qi][7] = fmaf(p[qi], vb.w, acc[qi][7]);
            }
        }
        __syncthreads();   // Vs/Ps reads done before next tile overwrites
    }

    // --- epilogue: normalize + write [B,S,D] layout ---
    float* outp = g_attn + ((size_t)(b*S_ + q0)) * D_ + h * HD_;
    #pragma unroll
    for (int qi = 0; qi < 4; qi++) {
        float inv = 1.0f / lrow[qi];
        int q = qg + 32*qi;
        float4 o;
        o.x = acc[qi][0]*inv; o.y = acc[qi][1]*inv;
        o.z = acc[qi][2]*inv; o.w = acc[qi][3]*inv;
        *(float4*)&outp[(size_t)q * D_ + c*8] = o;
        o.x = acc[qi][4]*inv; o.y = acc[qi][5]*inv;
        o.z = acc[qi][6]*inv; o.w = acc[qi][7]*inv;
        *(float4*)&outp[(size_t)q * D_ + c*8 + 4] = o;
    }
}

// ---------------------------------------------------------------------------
extern "C" void kernel_launch(void* const* d_in, const int* in_sizes, int n_in,
                              void* d_out, int out_size)
{
    const float* xq  = (const float*)d_in[0];
    const float* xk  = (const float*)d_in[1];
    const float* xv  = (const float*)d_in[2];
    const int*   msk = (const int*)  d_in[3];
    const float* wq  = (const float*)d_in[4];
    const float* bq  = (const float*)d_in[5];
    const float* wk  = (const float*)d_in[6];
    const float* bk  = (const float*)d_in[7];
    const float* wv  = (const float*)d_in[8];
    const float* bv  = (const float*)d_in[9];
    const float* wo  = (const float*)d_in[10];
    const float* bo  = (const float*)d_in[11];

    float *qp, *kp, *vp, *ap;
    cudaGetSymbolAddress((void**)&qp, g_q);
    cudaGetSymbolAddress((void**)&kp, g_k);
    cudaGetSymbolAddress((void**)&vp, g_v);
    cudaGetSymbolAddress((void**)&ap, g_attn);

    const int attn_smem = (128*QSTRIDE + 64*QSTRIDE*2 + 128*PSTRIDE) * (int)sizeof(float);
    static bool attr_set = false;
    if (!attr_set) {
        cudaFuncSetAttribute(attn_kernel,
                             cudaFuncAttributeMaxDynamicSharedMemorySize, attn_smem);
        attr_set = true;
    }

    dim3 gg(D_/128, M_TOT/128);  // (8, 32)
    gemm_bias<1><<<gg, 256>>>(xq, wq, bq, qp);
    gemm_bias<1><<<gg, 256>>>(xk, wk, bk, kp);
    gemm_bias<1><<<gg, 256>>>(xv, wv, bv, vp);

    dim3 ga(S_/128, B_*H_);      // (16, 32)
    attn_kernel<<<ga, 256, attn_smem>>>(msk);

    gemm_bias<0><<<gg, 256>>>(ap, wo, bo, (float*)d_out);
}

// round 8
// speedup vs baseline: 2.1561x; 1.3726x over previous
#include <cuda_runtime.h>
#include <math.h>

#define B_  2
#define S_  2048
#define D_  1024
#define H_  16
#define HD_ 64
#define M_TOT (B_*S_)   // 4096

// Scratch (device globals — no runtime allocation allowed)
__device__ float g_q[B_*H_*S_*HD_];
__device__ float g_k[B_*H_*S_*HD_];
__device__ float g_v[B_*H_*S_*HD_];
__device__ float g_attn[B_*S_*D_];
__device__ int   g_idx[B_*S_];   // compacted unmasked-key indices per batch
__device__ int   g_kc[B_];       // count of unmasked keys per batch

// ---------------------------------------------------------------------------
// Mask compaction: one block per batch. Masked keys (mask==0) contribute
// exp(-1e9 - m) == 0.0f exactly in fp32, so skipping them is bit-equivalent.
// ---------------------------------------------------------------------------
__global__ __launch_bounds__(256)
void mask_scan(const int* __restrict__ mask)
{
    __shared__ int cnts[256];
    __shared__ int offs[257];
    const int b   = blockIdx.x;
    const int tid = threadIdx.x;
    const int* m  = mask + b * S_;
    const int base = tid * 8;                 // 256 threads x 8 elems = 2048

    int loc[8];
    int cnt = 0;
    #pragma unroll
    for (int i = 0; i < 8; i++) {
        loc[i] = cnt;
        cnt += (m[base + i] != 0);
    }
    cnts[tid] = cnt;
    __syncthreads();
    if (tid == 0) {
        int s = 0;
        for (int i = 0; i < 256; i++) { offs[i] = s; s += cnts[i]; }
        offs[256] = s;
        g_kc[b] = s;
    }
    __syncthreads();
    const int off = offs[tid];
    #pragma unroll
    for (int i = 0; i < 8; i++)
        if (m[base + i] != 0)
            g_idx[b * S_ + off + loc[i]] = base + i;
}

// ---------------------------------------------------------------------------
// GEMM: C = A @ W^T + bias.   A:[M,K] row-major, W:[N,K] row-major.
// 128x128 tile, BK=16, 256 threads, 8x8 register tile (measured ~fp32 peak).
// SPLIT=1: scatter output to [B,H,S,HD] layout (for Q/K/V).
// ---------------------------------------------------------------------------
template<int SPLIT>
__global__ __launch_bounds__(256)
void gemm_bias(const float* __restrict__ A, const float* __restrict__ W,
               const float* __restrict__ bias, float* __restrict__ C)
{
    const int K = D_;
    __shared__ float As[16][128];
    __shared__ float Ws[16][128];

    const int tid = threadIdx.x;
    const int m0 = blockIdx.y * 128;
    const int n0 = blockIdx.x * 128;
    const int ar = tid >> 2;
    const int ac = (tid & 3) * 4;
    const int ty = tid >> 4;
    const int tx = tid & 15;

    float acc[8][8];
    #pragma unroll
    for (int i = 0; i < 8; i++)
        #pragma unroll
        for (int j = 0; j < 8; j++) acc[i][j] = 0.f;

    for (int k0 = 0; k0 < K; k0 += 16) {
        #pragma unroll
        for (int rr = 0; rr < 2; rr++) {
            int row = ar + rr * 64;
            float4 av = *(const float4*)&A[(size_t)(m0 + row) * K + k0 + ac];
            As[ac+0][row] = av.x; As[ac+1][row] = av.y;
            As[ac+2][row] = av.z; As[ac+3][row] = av.w;
            float4 wv = *(const float4*)&W[(size_t)(n0 + row) * K + k0 + ac];
            Ws[ac+0][row] = wv.x; Ws[ac+1][row] = wv.y;
            Ws[ac+2][row] = wv.z; Ws[ac+3][row] = wv.w;
        }
        __syncthreads();
        #pragma unroll
        for (int kk = 0; kk < 16; kk++) {
            float a[8], b[8];
            *(float4*)&a[0] = *(const float4*)&As[kk][ty*8];
            *(float4*)&a[4] = *(const float4*)&As[kk][ty*8+4];
            *(float4*)&b[0] = *(const float4*)&Ws[kk][tx*8];
            *(float4*)&b[4] = *(const float4*)&Ws[kk][tx*8+4];
            #pragma unroll
            for (int i = 0; i < 8; i++)
                #pragma unroll
                for (int j = 0; j < 8; j++)
                    acc[i][j] += a[i] * b[j];
        }
        __syncthreads();
    }

    #pragma unroll
    for (int i = 0; i < 8; i++) {
        int m = m0 + ty*8 + i;
        #pragma unroll
        for (int j4 = 0; j4 < 2; j4++) {
            int n = n0 + tx*8 + j4*4;
            float4 v;
            v.x = acc[i][j4*4+0] + bias[n+0];
            v.y = acc[i][j4*4+1] + bias[n+1];
            v.z = acc[i][j4*4+2] + bias[n+2];
            v.w = acc[i][j4*4+3] + bias[n+3];
            if (SPLIT) {
                int b  = m >> 11;
                int s  = m & (S_ - 1);
                int h  = n >> 6;
                int hd = n & 63;
                *(float4*)&C[(size_t)(((b*H_ + h)*S_) + s) * HD_ + hd] = v;
            } else {
                *(float4*)&C[(size_t)m * D_ + n] = v;
            }
        }
    }
}

// ---------------------------------------------------------------------------
// Flash-style attention over COMPACTED keys.
// Block tile: 128 queries x 64 (compacted) keys for one (b,h). 256 threads.
// Thread = (qg, c): q rows {qg+32*qi}, score cols j=jj*8+c, out dims c*8..+7.
// K/V rows gathered through g_idx (row reads stay coalesced). No mask loads;
// only the final partial tile needs the j<kc bounds predicate.
// ---------------------------------------------------------------------------
#define QSTRIDE 68   // 64 + 4 pad, float4-aligned
#define PSTRIDE 65

__global__ __launch_bounds__(256, 2)
void attn_kernel()
{
    extern __shared__ float sm[];
    float* Qs = sm;                        // 128*68
    float* Ks = Qs + 128*QSTRIDE;          // 64*68
    float* Vs = Ks + 64*QSTRIDE;           // 64*68
    float* Ps = Vs + 64*QSTRIDE;           // 128*65

    const int tid = threadIdx.x;
    const int bh  = blockIdx.y;
    const int b   = bh >> 4;
    const int h   = bh & 15;
    const int q0  = blockIdx.x * 128;
    const int qg  = tid >> 3;
    const int c   = tid & 7;

    const float* qbase = g_q + ((size_t)bh * S_ + q0) * HD_;
    const float* kbase = g_k + (size_t)bh * S_ * HD_;
    const float* vbase = g_v + (size_t)bh * S_ * HD_;
    const int*   idxp  = g_idx + b * S_;
    const int    kc    = g_kc[b];
    const int    ntile = (kc + 63) >> 6;

    // Load Q tile (128 rows x 16 float4, coalesced)
    for (int i = tid; i < 128*16; i += 256) {
        int r = i >> 4, c4 = (i & 15) << 2;
        *(float4*)&Qs[r*QSTRIDE + c4] = *(const float4*)&qbase[r*64 + c4];
    }

    float mrow[4] = {-1e30f, -1e30f, -1e30f, -1e30f};
    float lrow[4] = {0.f, 0.f, 0.f, 0.f};
    float acc[4][8];
    #pragma unroll
    for (int qi = 0; qi < 4; qi++)
        #pragma unroll
        for (int dd = 0; dd < 8; dd++) acc[qi][dd] = 0.f;

    __syncthreads();

    for (int kt = 0; kt < ntile; kt++) {
        const int jb = kt * 64;
        // --- gather K and V tiles via compacted indices ---
        for (int i = tid; i < 64*16; i += 256) {
            int r = i >> 4, c4 = (i & 15) << 2;
            int src = (jb + r < kc) ? idxp[jb + r] : idxp[0];
            *(float4*)&Ks[r*QSTRIDE + c4] = *(const float4*)&kbase[(size_t)src*64 + c4];
            *(float4*)&Vs[r*QSTRIDE + c4] = *(const float4*)&vbase[(size_t)src*64 + c4];
        }
        __syncthreads();

        // --- scores ---
        float s[4][8];
        #pragma unroll
        for (int qi = 0; qi < 4; qi++)
            #pragma unroll
            for (int jj = 0; jj < 8; jj++) s[qi][jj] = 0.f;

        #pragma unroll 4
        for (int d4 = 0; d4 < 64; d4 += 4) {
            float4 qv[4];
            #pragma unroll
            for (int qi = 0; qi < 4; qi++)
                qv[qi] = *(const float4*)&Qs[(qg + 32*qi)*QSTRIDE + d4];
            #pragma unroll
            for (int jj = 0; jj < 8; jj++) {
                float4 kv = *(const float4*)&Ks[(jj*8 + c)*QSTRIDE + d4];
                #pragma unroll
                for (int qi = 0; qi < 4; qi++) {
                    s[qi][jj] = fmaf(qv[qi].x, kv.x, s[qi][jj]);
                    s[qi][jj] = fmaf(qv[qi].y, kv.y, s[qi][jj]);
                    s[qi][jj] = fmaf(qv[qi].z, kv.z, s[qi][jj]);
                    s[qi][jj] = fmaf(qv[qi].w, kv.w, s[qi][jj]);
                }
            }
        }

        // --- scale + tail-bounds predicate (replaces mask load) ---
        #pragma unroll
        for (int jj = 0; jj < 8; jj++) {
            bool ok = (jb + jj*8 + c) < kc;
            #pragma unroll
            for (int qi = 0; qi < 4; qi++)
                s[qi][jj] = ok ? s[qi][jj] * 0.125f : -1.0e9f;
        }

        // --- online softmax update ---
        float t[4];
        #pragma unroll
        for (int qi = 0; qi < 4; qi++) {
            t[qi] = s[qi][0];
            #pragma unroll
            for (int jj = 1; jj < 8; jj++) t[qi] = fmaxf(t[qi], s[qi][jj]);
        }
        #pragma unroll
        for (int o = 1; o < 8; o <<= 1)
            #pragma unroll
            for (int qi = 0; qi < 4; qi++)
                t[qi] = fmaxf(t[qi], __shfl_xor_sync(0xffffffffu, t[qi], o));

        float cor[4], ps[4];
        #pragma unroll
        for (int qi = 0; qi < 4; qi++) {
            float mn = fmaxf(mrow[qi], t[qi]);
            cor[qi] = __expf(mrow[qi] - mn);
            mrow[qi] = mn;
            ps[qi] = 0.f;
            #pragma unroll
            for (int jj = 0; jj < 8; jj++) {
                float p = __expf(s[qi][jj] - mn);
                Ps[(qg + 32*qi)*PSTRIDE + jj*8 + c] = p;
                ps[qi] += p;
            }
        }
        #pragma unroll
        for (int o = 1; o < 8; o <<= 1)
            #pragma unroll
            for (int qi = 0; qi < 4; qi++)
                ps[qi] += __shfl_xor_sync(0xffffffffu, ps[qi], o);
        #pragma unroll
        for (int qi = 0; qi < 4; qi++) {
            lrow[qi] = lrow[qi]*cor[qi] + ps[qi];
            #pragma unroll
            for (int dd = 0; dd < 8; dd++) acc[qi][dd] *= cor[qi];
        }

        __syncthreads();

        // --- PV accumulate ---
        #pragma unroll 2
        for (int j = 0; j < 64; j++) {
            float p[4];
            #pragma unroll
            for (int qi = 0; qi < 4; qi++)
                p[qi] = Ps[(qg + 32*qi)*PSTRIDE + j];
            float4 va = *(const float4*)&Vs[j*QSTRIDE + c*8];
            float4 vb = *(const float4*)&Vs[j*QSTRIDE + c*8 + 4];
            #pragma unroll
            for (int qi = 0; qi < 4; qi++) {
                acc[qi][0] = fmaf(p[qi], va.x, acc[qi][0]);
                acc[qi][1] = fmaf(p[qi], va.y, acc[qi][1]);
                acc[qi][2] = fmaf(p[qi], va.z, acc[qi][2]);
                acc[qi][3] = fmaf(p[qi], va.w, acc[qi][3]);
                acc[qi][4] = fmaf(p[qi], vb.x, acc[qi][4]);
                acc[qi][5] = fmaf(p[qi], vb.y, acc[qi][5]);
                acc[qi][6] = fmaf(p[qi], vb.z, acc[qi][6]);
                acc[qi][7] = fmaf(p[qi], vb.w, acc[qi][7]);
            }
        }
        __syncthreads();
    }

    // --- epilogue: normalize + write [B,S,D] layout ---
    float* outp = g_attn + ((size_t)(b*S_ + q0)) * D_ + h * HD_;
    #pragma unroll
    for (int qi = 0; qi < 4; qi++) {
        float inv = 1.0f / lrow[qi];
        int q = qg + 32*qi;
        float4 o;
        o.x = acc[qi][0]*inv; o.y = acc[qi][1]*inv;
        o.z = acc[qi][2]*inv; o.w = acc[qi][3]*inv;
        *(float4*)&outp[(size_t)q * D_ + c*8] = o;
        o.x = acc[qi][4]*inv; o.y = acc[qi][5]*inv;
        o.z = acc[qi][6]*inv; o.w = acc[qi][7]*inv;
        *(float4*)&outp[(size_t)q * D_ + c*8 + 4] = o;
    }
}

// ---------------------------------------------------------------------------
extern "C" void kernel_launch(void* const* d_in, const int* in_sizes, int n_in,
                              void* d_out, int out_size)
{
    const float* xq  = (const float*)d_in[0];
    const float* xk  = (const float*)d_in[1];
    const float* xv  = (const float*)d_in[2];
    const int*   msk = (const int*)  d_in[3];
    const float* wq  = (const float*)d_in[4];
    const float* bq  = (const float*)d_in[5];
    const float* wk  = (const float*)d_in[6];
    const float* bk  = (const float*)d_in[7];
    const float* wv  = (const float*)d_in[8];
    const float* bv  = (const float*)d_in[9];
    const float* wo  = (const float*)d_in[10];
    const float* bo  = (const float*)d_in[11];

    float *qp, *kp, *vp, *ap;
    cudaGetSymbolAddress((void**)&qp, g_q);
    cudaGetSymbolAddress((void**)&kp, g_k);
    cudaGetSymbolAddress((void**)&vp, g_v);
    cudaGetSymbolAddress((void**)&ap, g_attn);

    const int attn_smem = (128*QSTRIDE + 64*QSTRIDE*2 + 128*PSTRIDE) * (int)sizeof(float);
    static bool attr_set = false;
    if (!attr_set) {
        cudaFuncSetAttribute(attn_kernel,
                             cudaFuncAttributeMaxDynamicSharedMemorySize, attn_smem);
        attr_set = true;
    }

    mask_scan<<<B_, 256>>>(msk);

    dim3 gg(D_/128, M_TOT/128);  // (8, 32)
    gemm_bias<1><<<gg, 256>>>(xq, wq, bq, qp);
    gemm_bias<1><<<gg, 256>>>(xk, wk, bk, kp);
    gemm_bias<1><<<gg, 256>>>(xv, wv, bv, vp);

    dim3 ga(S_/128, B_*H_);      // (16, 32)
    attn_kernel<<<ga, 256, attn_smem>>>();

    gemm_bias<0><<<gg, 256>>>(ap, wo, bo, (float*)d_out);
}